// round 4
// baseline (speedup 1.0000x reference)
#include <cuda_runtime.h>
#include <math.h>

#define IMG 40
#define HW 1600
#define BATCH 256
#define CH 40

typedef unsigned long long u64;

// Ping-pong scratch (131 MB each), device-side only.
__device__ float2 g_bufA[(size_t)BATCH * CH * HW];
__device__ float2 g_bufB[(size_t)BATCH * CH * HW];
__device__ float2 g_D[HW];   // forward DFT matrix (ortho norm per 1D pass)

template <int B>
__device__ __forceinline__ float2* getbuf() {
    return (B == 0) ? g_bufA : g_bufB;
}

__global__ void init_D_kernel() {
    int idx = blockIdx.x * blockDim.x + threadIdx.x;
    if (idx >= HW) return;
    int k = idx / IMG, n = idx % IMG;
    int m = (k * n) % IMG;
    float theta = 2.0f * 3.14159265358979323846f * (float)m / (float)IMG;
    float s, c;
    sincosf(theta, &s, &c);
    float nrm = rsqrtf((float)IMG);
    g_D[idx] = make_float2(c * nrm, -s * nrm);
}

// ---------------- packed f32x2 helpers ----------------
__device__ __forceinline__ u64 pack2(float lo, float hi) {
    u64 r; asm("mov.b64 %0, {%1, %2};" : "=l"(r) : "f"(lo), "f"(hi)); return r;
}
__device__ __forceinline__ float2 unpack2(u64 v) {
    float lo, hi; asm("mov.b64 {%0, %1}, %2;" : "=f"(lo), "=f"(hi) : "l"(v));
    return make_float2(lo, hi);
}
__device__ __forceinline__ void fma2(u64& a, u64 x, u64 y) {
    asm("fma.rn.f32x2 %0, %1, %2, %0;" : "+l"(a) : "l"(x), "l"(y));
}
__device__ __forceinline__ u64 add2(u64 a, u64 b) {
    u64 r; asm("add.rn.f32x2 %0, %1, %2;" : "=l"(r) : "l"(a), "l"(b)); return r;
}
__device__ __forceinline__ u64 sub2(u64 a, u64 b) {   // a - b = fma(b, -1, a)
    u64 r;
    asm("fma.rn.f32x2 %0, %1, %2, %3;"
        : "=l"(r) : "l"(b), "l"(0xBF800000BF800000ULL), "l"(a));
    return r;
}

// ---------------------------------------------------------------------------
// Pair-of-images 2D DFT core, packed f32x2. ZT float4 = (re0, re1, im0, im1).
// Thread t: k0=t%20 (cols k0,k0+20), r0=t/20 (rows r0,r0+20).
// P/Q/R/S accumulation; CONJ resolved by combine signs (exact fp32 either way):
//   forward: re = P - Q, im = R + S      (P=Σzre*dre, Q=Σzim*dim,
//   conj:    re = P + Q, im = S - R       R=Σzre*dim, S=Σzim*dre)
// Caller must __syncthreads() after filling ZT. No trailing sync.
// Results: outre/outim[ri][ci] = packed (img0,img1) at row r0+20ri, col k0+20ci.
// ---------------------------------------------------------------------------
template <bool CONJ>
__device__ __forceinline__ void dft2d_pair(
    float4 (*ZT)[IMG + 1], const float2 (*Ds)[IMG + 1],
    int k0, int r0, u64 outre[2][2], u64 outim[2][2])
{
    u64 P[2][2], Q[2][2], R[2][2], S[2][2];
    #pragma unroll
    for (int i = 0; i < 2; i++)
        #pragma unroll
        for (int j = 0; j < 2; j++) { P[i][j]=0; Q[i][j]=0; R[i][j]=0; S[i][j]=0; }

    // Pass 1: T(r,k) = sum_w Z(r,w) * D(k,w)
    #pragma unroll 4
    for (int w = 0; w < IMG; w++) {
        float4 za = ZT[r0][w];
        float4 zb = ZT[r0 + 20][w];
        float2 d0 = Ds[w][k0];
        float2 d1 = Ds[w][k0 + 20];
        u64 zreA = pack2(za.x, za.y), zimA = pack2(za.z, za.w);
        u64 zreB = pack2(zb.x, zb.y), zimB = pack2(zb.z, zb.w);
        u64 d0re = pack2(d0.x, d0.x), d0im = pack2(d0.y, d0.y);
        u64 d1re = pack2(d1.x, d1.x), d1im = pack2(d1.y, d1.y);
        fma2(P[0][0], zreA, d0re); fma2(Q[0][0], zimA, d0im);
        fma2(R[0][0], zreA, d0im); fma2(S[0][0], zimA, d0re);
        fma2(P[0][1], zreA, d1re); fma2(Q[0][1], zimA, d1im);
        fma2(R[0][1], zreA, d1im); fma2(S[0][1], zimA, d1re);
        fma2(P[1][0], zreB, d0re); fma2(Q[1][0], zimB, d0im);
        fma2(R[1][0], zreB, d0im); fma2(S[1][0], zimB, d0re);
        fma2(P[1][1], zreB, d1re); fma2(Q[1][1], zimB, d1im);
        fma2(R[1][1], zreB, d1im); fma2(S[1][1], zimB, d1re);
    }
    __syncthreads();   // pass-1 reads done; safe to overwrite ZT in place
    #pragma unroll
    for (int i = 0; i < 2; i++) {
        #pragma unroll
        for (int j = 0; j < 2; j++) {
            u64 re = CONJ ? add2(P[i][j], Q[i][j]) : sub2(P[i][j], Q[i][j]);
            u64 im = CONJ ? sub2(S[i][j], R[i][j]) : add2(R[i][j], S[i][j]);
            float2 rf = unpack2(re), mf = unpack2(im);
            ZT[r0 + 20 * i][k0 + 20 * j] = make_float4(rf.x, rf.y, mf.x, mf.y);
        }
    }
    __syncthreads();

    #pragma unroll
    for (int i = 0; i < 2; i++)
        #pragma unroll
        for (int j = 0; j < 2; j++) { P[i][j]=0; Q[i][j]=0; R[i][j]=0; S[i][j]=0; }

    // Pass 2: out(r,k) = sum_h T(h,k) * D(r,h).  [ri] -> D row, [ci] -> T col.
    #pragma unroll 4
    for (int h = 0; h < IMG; h++) {
        float4 t0 = ZT[h][k0];
        float4 t1 = ZT[h][k0 + 20];
        float2 d0 = Ds[h][r0];
        float2 d1 = Ds[h][r0 + 20];
        u64 tre0 = pack2(t0.x, t0.y), tim0 = pack2(t0.z, t0.w);
        u64 tre1 = pack2(t1.x, t1.y), tim1 = pack2(t1.z, t1.w);
        u64 d0re = pack2(d0.x, d0.x), d0im = pack2(d0.y, d0.y);
        u64 d1re = pack2(d1.x, d1.x), d1im = pack2(d1.y, d1.y);
        fma2(P[0][0], tre0, d0re); fma2(Q[0][0], tim0, d0im);
        fma2(R[0][0], tre0, d0im); fma2(S[0][0], tim0, d0re);
        fma2(P[0][1], tre1, d0re); fma2(Q[0][1], tim1, d0im);
        fma2(R[0][1], tre1, d0im); fma2(S[0][1], tim1, d0re);
        fma2(P[1][0], tre0, d1re); fma2(Q[1][0], tim0, d1im);
        fma2(R[1][0], tre0, d1im); fma2(S[1][0], tim0, d1re);
        fma2(P[1][1], tre1, d1re); fma2(Q[1][1], tim1, d1im);
        fma2(R[1][1], tre1, d1im); fma2(S[1][1], tim1, d1re);
    }
    #pragma unroll
    for (int i = 0; i < 2; i++) {
        #pragma unroll
        for (int j = 0; j < 2; j++) {
            outre[i][j] = CONJ ? add2(P[i][j], Q[i][j]) : sub2(P[i][j], Q[i][j]);
            outim[i][j] = CONJ ? sub2(S[i][j], R[i][j]) : add2(R[i][j], S[i][j]);
        }
    }
}

__device__ __forceinline__ void load_D_smem(float2 (*Ds)[IMG + 1], int t) {
    #pragma unroll
    for (int r = 0; r < 4; r++) {
        int idx = t + 400 * r;
        Ds[idx / IMG][idx % IMG] = g_D[idx];
    }
}

// ---------------------------------------------------------------------------
// First: forward FFT of real input x (2 images/block) -> freq in DST.
// ---------------------------------------------------------------------------
template <int DST>
__global__ __launch_bounds__(400, 2) void fft_first_kernel(const float* __restrict__ x)
{
    __shared__ float4 ZT[IMG][IMG + 1];
    __shared__ float2 Ds[IMG][IMG + 1];
    const int t = threadIdx.x;
    const size_t i0 = (size_t)blockIdx.x * 2;
    load_D_smem(Ds, t);
    const float* in0 = x + i0 * HW;
    const float* in1 = in0 + HW;
    #pragma unroll
    for (int r = 0; r < 4; r++) {
        int idx = t + 400 * r;
        ZT[idx / IMG][idx % IMG] = make_float4(in0[idx], in1[idx], 0.f, 0.f);
    }
    __syncthreads();
    const int k0 = t % 20, r0 = t / 20;
    u64 re[2][2], im[2][2];
    dft2d_pair<false>(ZT, Ds, k0, r0, re, im);
    float2* o0 = getbuf<DST>() + i0 * HW;
    float2* o1 = o0 + HW;
    #pragma unroll
    for (int ri = 0; ri < 2; ri++)
        #pragma unroll
        for (int ci = 0; ci < 2; ci++) {
            int p = (r0 + 20 * ri) * IMG + (k0 + 20 * ci);
            float2 rf = unpack2(re[ri][ci]), mf = unpack2(im[ri][ci]);
            o0[p] = make_float2(rf.x, mf.x);
            o1[p] = make_float2(rf.y, mf.y);
        }
}

// ---------------------------------------------------------------------------
// Fused boundary: freq SRC -> ifft -> CReLU -> fft -> freq DST. 2 img/block.
// ---------------------------------------------------------------------------
template <int SRC, int DST>
__global__ __launch_bounds__(400, 2) void fused_ifft_crelu_fft_kernel()
{
    __shared__ float4 ZT[IMG][IMG + 1];
    __shared__ float2 Ds[IMG][IMG + 1];
    const int t = threadIdx.x;
    const size_t i0 = (size_t)blockIdx.x * 2;
    load_D_smem(Ds, t);
    const float2* in0 = getbuf<SRC>() + i0 * HW;
    const float2* in1 = in0 + HW;
    #pragma unroll
    for (int r = 0; r < 4; r++) {
        int idx = t + 400 * r;
        float2 v0 = in0[idx], v1 = in1[idx];
        ZT[idx / IMG][idx % IMG] = make_float4(v0.x, v1.x, v0.y, v1.y);
    }
    __syncthreads();

    const int k0 = t % 20, r0 = t / 20;
    u64 re[2][2], im[2][2];
    dft2d_pair<true>(ZT, Ds, k0, r0, re, im);   // inverse FFT

    __syncthreads();   // pass-2 reads done; safe to repack
    #pragma unroll
    for (int ri = 0; ri < 2; ri++) {
        #pragma unroll
        for (int ci = 0; ci < 2; ci++) {
            float2 rf = unpack2(re[ri][ci]), mf = unpack2(im[ri][ci]);
            ZT[r0 + 20 * ri][k0 + 20 * ci] = make_float4(
                fmaxf(rf.x, 0.f), fmaxf(rf.y, 0.f),
                fmaxf(mf.x, 0.f), fmaxf(mf.y, 0.f));
        }
    }
    __syncthreads();

    dft2d_pair<false>(ZT, Ds, k0, r0, re, im);  // forward FFT

    float2* o0 = getbuf<DST>() + i0 * HW;
    float2* o1 = o0 + HW;
    #pragma unroll
    for (int ri = 0; ri < 2; ri++)
        #pragma unroll
        for (int ci = 0; ci < 2; ci++) {
            int p = (r0 + 20 * ri) * IMG + (k0 + 20 * ci);
            float2 rf = unpack2(re[ri][ci]), mf = unpack2(im[ri][ci]);
            o0[p] = make_float2(rf.x, mf.x);
            o1[p] = make_float2(rf.y, mf.y);
        }
}

// ---------------------------------------------------------------------------
// Last: inverse FFT (2 images/block), write real part to harness output.
// ---------------------------------------------------------------------------
template <int SRC>
__global__ __launch_bounds__(400, 2) void ifft_last_kernel(float* __restrict__ outp)
{
    __shared__ float4 ZT[IMG][IMG + 1];
    __shared__ float2 Ds[IMG][IMG + 1];
    const int t = threadIdx.x;
    const size_t i0 = (size_t)blockIdx.x * 2;
    load_D_smem(Ds, t);
    const float2* in0 = getbuf<SRC>() + i0 * HW;
    const float2* in1 = in0 + HW;
    #pragma unroll
    for (int r = 0; r < 4; r++) {
        int idx = t + 400 * r;
        float2 v0 = in0[idx], v1 = in1[idx];
        ZT[idx / IMG][idx % IMG] = make_float4(v0.x, v1.x, v0.y, v1.y);
    }
    __syncthreads();
    const int k0 = t % 20, r0 = t / 20;
    u64 re[2][2], im[2][2];
    dft2d_pair<true>(ZT, Ds, k0, r0, re, im);
    float* o0 = outp + i0 * HW;
    float* o1 = o0 + HW;
    #pragma unroll
    for (int ri = 0; ri < 2; ri++)
        #pragma unroll
        for (int ci = 0; ci < 2; ci++) {
            int p = (r0 + 20 * ri) * IMG + (k0 + 20 * ci);
            float2 rf = unpack2(re[ri][ci]);
            o0[p] = rf.x;
            o1[p] = rf.y;
        }
}

// ---------------------------------------------------------------------------
// mix40 packed: O[b,o,hw] = sum_i F[b,i,hw] * W[i,o,hw], hw on lanes.
// f32x2 pairs over (o, o+1): W staged as float4 (re_o, re_o1, im_o, im_o1).
// Warp tile: 4 b x 8 o (4 o-pairs). Register accum 32 x u64.
// ---------------------------------------------------------------------------
template <int SRC, int DST>
__global__ __launch_bounds__(640, 1) void mix40_kernel(const float2* __restrict__ W)
{
    __shared__ float4 Ws4[2][20][32];   // [i][opair][hw]  20.5 KB
    __shared__ float2 Fs[16][2][32];    // [b][i][hw]       8 KB

    const float2* F = getbuf<SRC>();
    float2* O = getbuf<DST>();

    const int tid  = threadIdx.x;
    const int lane = tid & 31;
    const int warp = tid >> 5;
    const int bq   = (warp & 3) * 4;    // base b within 16-tile
    const int oq   = (warp >> 2) * 8;   // base o
    const int opq  = (warp >> 2) * 4;   // base o-pair
    const int hw0  = blockIdx.x * 32;
    const int b0   = blockIdx.y * 16;

    u64 accre[4][4], accim[4][4];
    #pragma unroll
    for (int b = 0; b < 4; b++)
        #pragma unroll
        for (int op = 0; op < 4; op++) { accre[b][op] = 0; accim[b][op] = 0; }

    for (int chunk = 0; chunk < 20; chunk++) {
        const int i0 = chunk * 2;
        // stage F: 16b x 2i x 32hw
        #pragma unroll
        for (int rep = 0; rep < 2; rep++) {
            int idx = tid + rep * 640;
            if (idx < 1024) {
                int b = idx >> 6, rem = idx & 63;
                int ii = rem >> 5, hw = rem & 31;
                Fs[b][ii][hw] = F[((size_t)(b0 + b) * CH + i0 + ii) * HW + hw0 + hw];
            }
        }
        // stage W into o-paired float4 layout
        #pragma unroll
        for (int rep = 0; rep < 4; rep++) {
            int idx = tid + rep * 640;
            int ii = idx / 1280, rem = idx % 1280;
            int o = rem >> 5, hw = rem & 31;
            float2 v = W[((size_t)(i0 + ii) * CH + o) * HW + hw0 + hw];
            float* base = (float*)&Ws4[ii][o >> 1][hw];
            base[(o & 1)]     = v.x;
            base[2 + (o & 1)] = v.y;
        }
        __syncthreads();
        #pragma unroll
        for (int ii = 0; ii < 2; ii++) {
            u64 wre[4], wim[4];
            #pragma unroll
            for (int op = 0; op < 4; op++) {
                float4 wv = Ws4[ii][opq + op][lane];
                wre[op] = pack2(wv.x, wv.y);
                wim[op] = pack2(wv.z, wv.w);
            }
            #pragma unroll
            for (int b = 0; b < 4; b++) {
                float2 f = Fs[bq + b][ii][lane];
                u64 fre  = pack2(f.x, f.x);
                u64 fim  = pack2(f.y, f.y);
                u64 nfim = pack2(-f.y, -f.y);
                #pragma unroll
                for (int op = 0; op < 4; op++) {
                    fma2(accre[b][op], fre,  wre[op]);
                    fma2(accre[b][op], nfim, wim[op]);
                    fma2(accim[b][op], fre,  wim[op]);
                    fma2(accim[b][op], fim,  wre[op]);
                }
            }
        }
        __syncthreads();
    }

    #pragma unroll
    for (int b = 0; b < 4; b++)
        #pragma unroll
        for (int op = 0; op < 4; op++) {
            float2 rf = unpack2(accre[b][op]), mf = unpack2(accim[b][op]);
            size_t row = ((size_t)(b0 + bq + b) * CH + oq + 2 * op) * HW + hw0 + lane;
            O[row]      = make_float2(rf.x, mf.x);
            O[row + HW] = make_float2(rf.y, mf.y);
        }
}

// Layer-1 mix (inC=1): O[b,o,hw] = F[b,hw] * W1[o,hw]. Fully coalesced.
template <int SRC, int DST>
__global__ __launch_bounds__(400) void mix1_kernel(const float2* __restrict__ W)
{
    const float2* F = getbuf<SRC>();
    float2* O = getbuf<DST>();
    const int o = blockIdx.x;
    const int b = blockIdx.y;
    #pragma unroll
    for (int r = 0; r < 4; r++) {
        int hw = threadIdx.x + 400 * r;
        float2 f = F[(size_t)b * HW + hw];
        float2 w = W[(size_t)o * HW + hw];
        float2 acc;
        acc.x = f.x * w.x - f.y * w.y;
        acc.y = f.x * w.y + f.y * w.x;
        O[((size_t)b * CH + o) * HW + hw] = acc;
    }
}

// Layer-6 mix (outC=1): O[b,hw] = sum_i F[b,i,hw] * W6[i,hw]. Coalesced.
template <int SRC, int DST>
__global__ __launch_bounds__(400) void mix6_kernel(const float2* __restrict__ W)
{
    const float2* F = getbuf<SRC>();
    float2* O = getbuf<DST>();
    const int b = blockIdx.x;
    #pragma unroll
    for (int r = 0; r < 4; r++) {
        int hw = threadIdx.x + 400 * r;
        float2 acc = {0, 0};
        #pragma unroll 8
        for (int i = 0; i < CH; i++) {
            float2 f = F[((size_t)b * CH + i) * HW + hw];
            float2 w = W[(size_t)i * HW + hw];
            acc.x = fmaf(f.x, w.x, acc.x); acc.x = fmaf(-f.y, w.y, acc.x);
            acc.y = fmaf(f.x, w.y, acc.y); acc.y = fmaf(f.y, w.x, acc.y);
        }
        O[(size_t)b * HW + hw] = acc;
    }
}

extern "C" void kernel_launch(void* const* d_in, const int* in_sizes, int n_in,
                              void* d_out, int out_size)
{
    const float*  x  = (const float*)d_in[0];
    const float2* w1 = (const float2*)d_in[1];
    const float2* w2 = (const float2*)d_in[2];
    const float2* w3 = (const float2*)d_in[3];
    const float2* w4 = (const float2*)d_in[4];
    const float2* w5 = (const float2*)d_in[5];
    const float2* w6 = (const float2*)d_in[6];
    float* out = (float*)d_out;

    const int nPair = BATCH * CH / 2;          // 5120 fused blocks
    const dim3 mixGrid(HW / 32, BATCH / 16);   // (50, 16)
    const dim3 mix1Grid(CH, BATCH);

    init_D_kernel<<<4, 400>>>();

    // Layer 1 (inC=1 -> outC=40)
    fft_first_kernel<0><<<BATCH / 2, 400>>>(x);              // x -> A (freq)
    mix1_kernel<0, 1><<<mix1Grid, 400>>>(w1);                // A -> B
    fused_ifft_crelu_fft_kernel<1, 0><<<nPair, 400>>>();     // B -> A

    // Layer 2
    mix40_kernel<0, 1><<<mixGrid, 640>>>(w2);                // A -> B
    fused_ifft_crelu_fft_kernel<1, 0><<<nPair, 400>>>();     // B -> A

    // Layer 3
    mix40_kernel<0, 1><<<mixGrid, 640>>>(w3);
    fused_ifft_crelu_fft_kernel<1, 0><<<nPair, 400>>>();

    // Layer 4
    mix40_kernel<0, 1><<<mixGrid, 640>>>(w4);
    fused_ifft_crelu_fft_kernel<1, 0><<<nPair, 400>>>();

    // Layer 5
    mix40_kernel<0, 1><<<mixGrid, 640>>>(w5);
    fused_ifft_crelu_fft_kernel<1, 0><<<nPair, 400>>>();     // B -> A

    // Layer 6 (inC=40 -> outC=1), final output = real(ifft2)
    mix6_kernel<0, 1><<<BATCH, 400>>>(w6);                   // A -> B
    ifft_last_kernel<1><<<BATCH / 2, 400>>>(out);            // B -> out
}

// round 5
// speedup vs baseline: 1.0974x; 1.0974x over previous
#include <cuda_runtime.h>
#include <math.h>

#define IMG 40
#define HW 1600
#define BATCH 256
#define CH 40

typedef unsigned long long u64;

// Ping-pong scratch (131 MB each), device-side only.
__device__ float2 g_bufA[(size_t)BATCH * CH * HW];
__device__ float2 g_bufB[(size_t)BATCH * CH * HW];
__device__ float2 g_D[HW];   // forward DFT matrix (ortho norm per 1D pass)

template <int B>
__device__ __forceinline__ float2* getbuf() {
    return (B == 0) ? g_bufA : g_bufB;
}

__global__ void init_D_kernel() {
    int idx = blockIdx.x * blockDim.x + threadIdx.x;
    if (idx >= HW) return;
    int k = idx / IMG, n = idx % IMG;
    int m = (k * n) % IMG;
    float theta = 2.0f * 3.14159265358979323846f * (float)m / (float)IMG;
    float s, c;
    sincosf(theta, &s, &c);
    float nrm = rsqrtf((float)IMG);
    g_D[idx] = make_float2(c * nrm, -s * nrm);
}

// ---------------- packed f32x2 helpers ----------------
__device__ __forceinline__ u64 pack2(float lo, float hi) {
    u64 r; asm("mov.b64 %0, {%1, %2};" : "=l"(r) : "f"(lo), "f"(hi)); return r;
}
__device__ __forceinline__ float2 unpack2(u64 v) {
    float lo, hi; asm("mov.b64 {%0, %1}, %2;" : "=f"(lo), "=f"(hi) : "l"(v));
    return make_float2(lo, hi);
}
__device__ __forceinline__ void fma2(u64& a, u64 x, u64 y) {
    asm("fma.rn.f32x2 %0, %1, %2, %0;" : "+l"(a) : "l"(x), "l"(y));
}
__device__ __forceinline__ u64 neg2(u64 a) {   // flip both sign bits (exact)
    u64 r;
    asm("xor.b64 %0, %1, %2;" : "=l"(r) : "l"(a), "l"(0x8000000080000000ULL));
    return r;
}

// ---------------------------------------------------------------------------
// 2D DFT of a pair of images held in ZT (float4 = re0, re1, im0, im1).
// 200 threads.  Pass 1 mapping: thread t -> rows {t/10, t/10+20} (2),
// cols {t%10 + 10ci} (4).  Pass 2 mapping: rows {t/20 + 10ri} (4),
// cols {t%20 + 20ci} (2).  Both passes hit 2.0 smem-bytes per fma2.
// Complex mac with re/im accumulators; conj handled by operand-role swap
// of (dim, -dim) — exact fp32 either way.
// Caller must __syncthreads() after filling ZT; no trailing sync.
// Output: outre/outim[ri][ci] packed (img0,img1) at (t/20+10ri, t%20+20ci).
// ---------------------------------------------------------------------------
template <bool CONJ>
__device__ __forceinline__ void dft2d(
    float4 (*ZT)[IMG + 1], const float2 (*Ds)[IMG + 1], int t,
    u64 outre[4][2], u64 outim[4][2])
{
    const int c0 = t % 10, r0 = t / 10;

    u64 are[2][4], aim[2][4];
    #pragma unroll
    for (int i = 0; i < 2; i++)
        #pragma unroll
        for (int j = 0; j < 4; j++) { are[i][j] = 0; aim[i][j] = 0; }

    // Pass 1: T(r,k) = sum_w Z(r,w) * D(k,w)
    #pragma unroll 4
    for (int w = 0; w < IMG; w++) {
        float4 za = ZT[r0][w];
        float4 zb = ZT[r0 + 20][w];
        u64 zreA = pack2(za.x, za.y), zimA = pack2(za.z, za.w);
        u64 zreB = pack2(zb.x, zb.y), zimB = pack2(zb.z, zb.w);
        #pragma unroll
        for (int ci = 0; ci < 4; ci++) {
            float2 d = Ds[w][c0 + 10 * ci];
            u64 dre2  = pack2(d.x, d.x);
            u64 dim2  = pack2(d.y, d.y);
            u64 dnim2 = neg2(dim2);
            u64 mre = CONJ ? dim2 : dnim2;   // multiplier of zim into re
            u64 mim = CONJ ? dnim2 : dim2;   // multiplier of zre into im
            fma2(are[0][ci], zreA, dre2); fma2(are[0][ci], zimA, mre);
            fma2(aim[0][ci], zreA, mim);  fma2(aim[0][ci], zimA, dre2);
            fma2(are[1][ci], zreB, dre2); fma2(are[1][ci], zimB, mre);
            fma2(aim[1][ci], zreB, mim);  fma2(aim[1][ci], zimB, dre2);
        }
    }
    __syncthreads();   // all pass-1 reads done; overwrite ZT in place
    #pragma unroll
    for (int ri = 0; ri < 2; ri++)
        #pragma unroll
        for (int ci = 0; ci < 4; ci++) {
            float2 rf = unpack2(are[ri][ci]), mf = unpack2(aim[ri][ci]);
            ZT[r0 + 20 * ri][c0 + 10 * ci] = make_float4(rf.x, rf.y, mf.x, mf.y);
        }
    __syncthreads();

    // Pass 2: out(r,k) = sum_h T(h,k) * D(r,h), remapped 4 rows x 2 cols.
    const int c2 = t % 20, r2 = t / 20;
    #pragma unroll
    for (int i = 0; i < 4; i++)
        #pragma unroll
        for (int j = 0; j < 2; j++) { outre[i][j] = 0; outim[i][j] = 0; }

    #pragma unroll 4
    for (int h = 0; h < IMG; h++) {
        float4 t0 = ZT[h][c2];
        float4 t1 = ZT[h][c2 + 20];
        u64 tre0 = pack2(t0.x, t0.y), tim0 = pack2(t0.z, t0.w);
        u64 tre1 = pack2(t1.x, t1.y), tim1 = pack2(t1.z, t1.w);
        #pragma unroll
        for (int ri = 0; ri < 4; ri++) {
            float2 d = Ds[h][r2 + 10 * ri];
            u64 dre2  = pack2(d.x, d.x);
            u64 dim2  = pack2(d.y, d.y);
            u64 dnim2 = neg2(dim2);
            u64 mre = CONJ ? dim2 : dnim2;
            u64 mim = CONJ ? dnim2 : dim2;
            fma2(outre[ri][0], tre0, dre2); fma2(outre[ri][0], tim0, mre);
            fma2(outim[ri][0], tre0, mim);  fma2(outim[ri][0], tim0, dre2);
            fma2(outre[ri][1], tre1, dre2); fma2(outre[ri][1], tim1, mre);
            fma2(outim[ri][1], tre1, mim);  fma2(outim[ri][1], tim1, dre2);
        }
    }
}

__device__ __forceinline__ void load_D_smem(float2 (*Ds)[IMG + 1], int t) {
    #pragma unroll
    for (int r = 0; r < 8; r++) {
        int idx = t + 200 * r;
        Ds[idx / IMG][idx % IMG] = g_D[idx];
    }
}

// ---------------------------------------------------------------------------
// First: forward FFT of real input x (2 images/block) -> freq in DST.
// ---------------------------------------------------------------------------
template <int DST>
__global__ __launch_bounds__(200, 4) void fft_first_kernel(const float* __restrict__ x)
{
    __shared__ float4 ZT[IMG][IMG + 1];
    __shared__ float2 Ds[IMG][IMG + 1];
    const int t = threadIdx.x;
    const size_t i0 = (size_t)blockIdx.x * 2;
    load_D_smem(Ds, t);
    const float* in0 = x + i0 * HW;
    const float* in1 = in0 + HW;
    #pragma unroll
    for (int r = 0; r < 8; r++) {
        int idx = t + 200 * r;
        ZT[idx / IMG][idx % IMG] = make_float4(in0[idx], in1[idx], 0.f, 0.f);
    }
    __syncthreads();
    u64 re[4][2], im[4][2];
    dft2d<false>(ZT, Ds, t, re, im);
    const int c2 = t % 20, r2 = t / 20;
    float2* o0 = getbuf<DST>() + i0 * HW;
    float2* o1 = o0 + HW;
    #pragma unroll
    for (int ri = 0; ri < 4; ri++)
        #pragma unroll
        for (int ci = 0; ci < 2; ci++) {
            int p = (r2 + 10 * ri) * IMG + (c2 + 20 * ci);
            float2 rf = unpack2(re[ri][ci]), mf = unpack2(im[ri][ci]);
            o0[p] = make_float2(rf.x, mf.x);
            o1[p] = make_float2(rf.y, mf.y);
        }
}

// ---------------------------------------------------------------------------
// Fused boundary: freq SRC -> ifft -> CReLU -> fft -> freq DST. 2 img/block.
// ---------------------------------------------------------------------------
template <int SRC, int DST>
__global__ __launch_bounds__(200, 4) void fused_ifft_crelu_fft_kernel()
{
    __shared__ float4 ZT[IMG][IMG + 1];
    __shared__ float2 Ds[IMG][IMG + 1];
    const int t = threadIdx.x;
    const size_t i0 = (size_t)blockIdx.x * 2;
    load_D_smem(Ds, t);
    const float2* in0 = getbuf<SRC>() + i0 * HW;
    const float2* in1 = in0 + HW;
    #pragma unroll
    for (int r = 0; r < 8; r++) {
        int idx = t + 200 * r;
        float2 v0 = in0[idx], v1 = in1[idx];
        ZT[idx / IMG][idx % IMG] = make_float4(v0.x, v1.x, v0.y, v1.y);
    }
    __syncthreads();

    u64 re[4][2], im[4][2];
    dft2d<true>(ZT, Ds, t, re, im);     // inverse FFT

    const int c2 = t % 20, r2 = t / 20;
    __syncthreads();   // pass-2 reads done; safe to repack
    #pragma unroll
    for (int ri = 0; ri < 4; ri++)
        #pragma unroll
        for (int ci = 0; ci < 2; ci++) {
            float2 rf = unpack2(re[ri][ci]), mf = unpack2(im[ri][ci]);
            ZT[r2 + 10 * ri][c2 + 20 * ci] = make_float4(
                fmaxf(rf.x, 0.f), fmaxf(rf.y, 0.f),
                fmaxf(mf.x, 0.f), fmaxf(mf.y, 0.f));
        }
    __syncthreads();

    dft2d<false>(ZT, Ds, t, re, im);    // forward FFT

    float2* o0 = getbuf<DST>() + i0 * HW;
    float2* o1 = o0 + HW;
    #pragma unroll
    for (int ri = 0; ri < 4; ri++)
        #pragma unroll
        for (int ci = 0; ci < 2; ci++) {
            int p = (r2 + 10 * ri) * IMG + (c2 + 20 * ci);
            float2 rf = unpack2(re[ri][ci]), mf = unpack2(im[ri][ci]);
            o0[p] = make_float2(rf.x, mf.x);
            o1[p] = make_float2(rf.y, mf.y);
        }
}

// ---------------------------------------------------------------------------
// Last: inverse FFT (2 images/block), write real part to harness output.
// ---------------------------------------------------------------------------
template <int SRC>
__global__ __launch_bounds__(200, 4) void ifft_last_kernel(float* __restrict__ outp)
{
    __shared__ float4 ZT[IMG][IMG + 1];
    __shared__ float2 Ds[IMG][IMG + 1];
    const int t = threadIdx.x;
    const size_t i0 = (size_t)blockIdx.x * 2;
    load_D_smem(Ds, t);
    const float2* in0 = getbuf<SRC>() + i0 * HW;
    const float2* in1 = in0 + HW;
    #pragma unroll
    for (int r = 0; r < 8; r++) {
        int idx = t + 200 * r;
        float2 v0 = in0[idx], v1 = in1[idx];
        ZT[idx / IMG][idx % IMG] = make_float4(v0.x, v1.x, v0.y, v1.y);
    }
    __syncthreads();
    u64 re[4][2], im[4][2];
    dft2d<true>(ZT, Ds, t, re, im);
    const int c2 = t % 20, r2 = t / 20;
    float* o0 = outp + i0 * HW;
    float* o1 = o0 + HW;
    #pragma unroll
    for (int ri = 0; ri < 4; ri++)
        #pragma unroll
        for (int ci = 0; ci < 2; ci++) {
            int p = (r2 + 10 * ri) * IMG + (c2 + 20 * ci);
            float2 rf = unpack2(re[ri][ci]);
            o0[p] = rf.x;
            o1[p] = rf.y;
        }
}

// ---------------------------------------------------------------------------
// mix40 (R3 version — fastest so far): O[b,o,hw] = sum_i F[b,i,hw]*W[i,o,hw],
// hw on lanes (coalesced). Warp tile 4b x 8o; F/W staged in i-chunks of 2.
// ---------------------------------------------------------------------------
__device__ __forceinline__ void cmac(float2& a, float2 z, float2 d) {
    a.x = fmaf(z.x, d.x, a.x);
    a.x = fmaf(-z.y, d.y, a.x);
    a.y = fmaf(z.x, d.y, a.y);
    a.y = fmaf(z.y, d.x, a.y);
}

template <int SRC, int DST>
__global__ __launch_bounds__(640, 1) void mix40_kernel(const float2* __restrict__ W)
{
    __shared__ float2 Fs[16][2][32];   // [b][i][hw]  8 KB
    __shared__ float2 Ws[2][40][32];   // [i][o][hw]  20.5 KB

    const float2* F = getbuf<SRC>();
    float2* O = getbuf<DST>();

    const int tid  = threadIdx.x;
    const int lane = tid & 31;
    const int warp = tid >> 5;
    const int bq   = (warp & 3) * 4;
    const int oq   = (warp >> 2) * 8;
    const int hw0  = blockIdx.x * 32;
    const int b0   = blockIdx.y * 16;

    float2 acc[4][8];
    #pragma unroll
    for (int b = 0; b < 4; b++)
        #pragma unroll
        for (int o = 0; o < 8; o++)
            acc[b][o] = make_float2(0.f, 0.f);

    for (int chunk = 0; chunk < 20; chunk++) {
        const int i0 = chunk * 2;
        #pragma unroll
        for (int rep = 0; rep < 2; rep++) {
            int idx = tid + rep * 640;
            if (idx < 1024) {
                int b = idx >> 6, rem = idx & 63;
                int ii = rem >> 5, hw = rem & 31;
                Fs[b][ii][hw] = F[((size_t)(b0 + b) * CH + i0 + ii) * HW + hw0 + hw];
            }
        }
        #pragma unroll
        for (int rep = 0; rep < 4; rep++) {
            int idx = tid + rep * 640;
            int ii = idx / 1280, rem = idx % 1280;
            int o = rem >> 5, hw = rem & 31;
            Ws[ii][o][hw] = W[((size_t)(i0 + ii) * CH + o) * HW + hw0 + hw];
        }
        __syncthreads();
        #pragma unroll
        for (int ii = 0; ii < 2; ii++) {
            float2 f[4], wv[8];
            #pragma unroll
            for (int b = 0; b < 4; b++) f[b] = Fs[bq + b][ii][lane];
            #pragma unroll
            for (int o = 0; o < 8; o++) wv[o] = Ws[ii][oq + o][lane];
            #pragma unroll
            for (int b = 0; b < 4; b++)
                #pragma unroll
                for (int o = 0; o < 8; o++)
                    cmac(acc[b][o], f[b], wv[o]);
        }
        __syncthreads();
    }

    #pragma unroll
    for (int b = 0; b < 4; b++)
        #pragma unroll
        for (int o = 0; o < 8; o++)
            O[((size_t)(b0 + bq + b) * CH + oq + o) * HW + hw0 + lane] = acc[b][o];
}

// Layer-1 mix (inC=1): O[b,o,hw] = F[b,hw] * W1[o,hw]. Fully coalesced.
template <int SRC, int DST>
__global__ __launch_bounds__(400) void mix1_kernel(const float2* __restrict__ W)
{
    const float2* F = getbuf<SRC>();
    float2* O = getbuf<DST>();
    const int o = blockIdx.x;
    const int b = blockIdx.y;
    #pragma unroll
    for (int r = 0; r < 4; r++) {
        int hw = threadIdx.x + 400 * r;
        float2 f = F[(size_t)b * HW + hw];
        float2 w = W[(size_t)o * HW + hw];
        float2 acc;
        acc.x = f.x * w.x - f.y * w.y;
        acc.y = f.x * w.y + f.y * w.x;
        O[((size_t)b * CH + o) * HW + hw] = acc;
    }
}

// Layer-6 mix (outC=1): O[b,hw] = sum_i F[b,i,hw] * W6[i,hw]. Coalesced.
template <int SRC, int DST>
__global__ __launch_bounds__(400) void mix6_kernel(const float2* __restrict__ W)
{
    const float2* F = getbuf<SRC>();
    float2* O = getbuf<DST>();
    const int b = blockIdx.x;
    #pragma unroll
    for (int r = 0; r < 4; r++) {
        int hw = threadIdx.x + 400 * r;
        float2 acc = {0, 0};
        #pragma unroll 8
        for (int i = 0; i < CH; i++) {
            float2 f = F[((size_t)b * CH + i) * HW + hw];
            float2 w = W[(size_t)i * HW + hw];
            cmac(acc, f, w);
        }
        O[(size_t)b * HW + hw] = acc;
    }
}

extern "C" void kernel_launch(void* const* d_in, const int* in_sizes, int n_in,
                              void* d_out, int out_size)
{
    const float*  x  = (const float*)d_in[0];
    const float2* w1 = (const float2*)d_in[1];
    const float2* w2 = (const float2*)d_in[2];
    const float2* w3 = (const float2*)d_in[3];
    const float2* w4 = (const float2*)d_in[4];
    const float2* w5 = (const float2*)d_in[5];
    const float2* w6 = (const float2*)d_in[6];
    float* out = (float*)d_out;

    const int nPair = BATCH * CH / 2;          // 5120 fused blocks
    const dim3 mixGrid(HW / 32, BATCH / 16);   // (50, 16)
    const dim3 mix1Grid(CH, BATCH);

    init_D_kernel<<<4, 400>>>();

    // Layer 1 (inC=1 -> outC=40)
    fft_first_kernel<0><<<BATCH / 2, 200>>>(x);              // x -> A (freq)
    mix1_kernel<0, 1><<<mix1Grid, 400>>>(w1);                // A -> B
    fused_ifft_crelu_fft_kernel<1, 0><<<nPair, 200>>>();     // B -> A

    // Layer 2
    mix40_kernel<0, 1><<<mixGrid, 640>>>(w2);                // A -> B
    fused_ifft_crelu_fft_kernel<1, 0><<<nPair, 200>>>();     // B -> A

    // Layer 3
    mix40_kernel<0, 1><<<mixGrid, 640>>>(w3);
    fused_ifft_crelu_fft_kernel<1, 0><<<nPair, 200>>>();

    // Layer 4
    mix40_kernel<0, 1><<<mixGrid, 640>>>(w4);
    fused_ifft_crelu_fft_kernel<1, 0><<<nPair, 200>>>();

    // Layer 5
    mix40_kernel<0, 1><<<mixGrid, 640>>>(w5);
    fused_ifft_crelu_fft_kernel<1, 0><<<nPair, 200>>>();     // B -> A

    // Layer 6 (inC=40 -> outC=1), final output = real(ifft2)
    mix6_kernel<0, 1><<<BATCH, 400>>>(w6);                   // A -> B
    ifft_last_kernel<1><<<BATCH / 2, 200>>>(out);            // B -> out
}